// round 14
// baseline (speedup 1.0000x reference)
#include <cuda_runtime.h>
#include <cuda_fp16.h>
#include <mma.h>

using namespace nvcuda;

#define N_NODES   100000
#define N_EDGES   3200000
#define F_IN      128
#define HID       64
#define N_GRAPHS  256
#define N_CLASSES 8
#define NB        391            // ceil(N_NODES / 256)

// ---------------- scratch (static device globals; no runtime allocs) ----------------
__device__ int    g_indeg[N_NODES];
__device__ int    g_off[N_NODES];
__device__ int    g_cursor[N_NODES];
__device__ int    g_blocksum[NB];
__device__ float  g_dis[N_NODES];
__device__ int    g_csr[N_EDGES];
__device__ uint4  g_xh[(size_t)N_NODES * 16];     // fp16 x (128 halves/node)
__device__ __half g_w1h[F_IN * HID];
__device__ __half g_w2h[HID * HID];
__device__ uint4  g_q1[(size_t)N_NODES * 4];      // int8 gemm1 rows (64 B/node), 16B-aligned
__device__ uint4  g_q2[(size_t)N_NODES * 4];      // int8 gemm2 rows (64 B/node)
__device__ float  g_s1[N_NODES];                  // layer1 row scale (dis folded in later)
__device__ float  g_s2[N_NODES];                  // layer2 row scale (dis included)
__device__ uint4  g_bufH[(size_t)N_NODES * 8];    // fp16 relu(gather1 + b1)  (gemm2 input)
__device__ float  g_pooled[N_GRAPHS * HID];       // fused pooling accumulator

// ---------------- stream-B prepass: W -> fp16 ----------------
__global__ void convw_kernel(const float* __restrict__ W1, const float* __restrict__ W2) {
    int i = blockIdx.x * blockDim.x + threadIdx.x;
    if (i < F_IN * HID) g_w1h[i] = __float2half(W1[i]);
    if (i < HID * HID) g_w2h[i] = __float2half(W2[i]);
}

// ---------------- stream-B prepass: x -> fp16 (8 floats/thread) ----------------
__global__ void xhalf_kernel(const float* __restrict__ x) {
    int i = blockIdx.x * blockDim.x + threadIdx.x;   // over N_NODES*16
    if (i >= N_NODES * 16) return;
    float4 a = ((const float4*)x)[(size_t)i * 2];
    float4 b = ((const float4*)x)[(size_t)i * 2 + 1];
    union { uint4 u; __half2 h[4]; } pk;
    pk.h[0] = __float22half2_rn(make_float2(a.x, a.y));
    pk.h[1] = __float22half2_rn(make_float2(a.z, a.w));
    pk.h[2] = __float22half2_rn(make_float2(b.x, b.y));
    pk.h[3] = __float22half2_rn(make_float2(b.z, b.w));
    g_xh[i] = pk.u;
}

// ---------------- stream-B: fold dis into layer-1 scale (after scan_local) ----------------
__global__ void foldscale_kernel() {
    int i = blockIdx.x * blockDim.x + threadIdx.x;
    if (i < N_NODES) g_s1[i] *= g_dis[i];
}

// ---------------- init: zero indeg + pooled ----------------
__global__ void zinit_kernel() {
    int i = blockIdx.x * blockDim.x + threadIdx.x;
    if (i < N_NODES) g_indeg[i] = 0;
    if (i < N_GRAPHS * HID) g_pooled[i] = 0.0f;
}

// ---------------- in-degree histogram over dst (4 edges/thread, int4 loads) ----------------
__global__ void hist_kernel(const int* __restrict__ ei) {
    int e = blockIdx.x * blockDim.x + threadIdx.x;
    if (e >= N_EDGES / 4) return;
    int4 dd = ((const int4*)(ei + N_EDGES))[e];
    atomicAdd(&g_indeg[dd.x], 1);
    atomicAdd(&g_indeg[dd.y], 1);
    atomicAdd(&g_indeg[dd.z], 1);
    atomicAdd(&g_indeg[dd.w], 1);
}

// ---------------- scan pass 1: per-block exclusive scan + block sums + dis ----------------
__global__ void scan_local_kernel() {
    __shared__ int s[256];
    int i = blockIdx.x * 256 + threadIdx.x;
    int v = (i < N_NODES) ? g_indeg[i] : 0;
    s[threadIdx.x] = v;
    __syncthreads();
    for (int d = 1; d < 256; d <<= 1) {
        int t = (threadIdx.x >= d) ? s[threadIdx.x - d] : 0;
        __syncthreads();
        s[threadIdx.x] += t;
        __syncthreads();
    }
    if (i < N_NODES) {
        g_off[i] = s[threadIdx.x] - v;
        g_dis[i] = rsqrtf((float)(v + 1));            // +1 self loop
    }
    if (threadIdx.x == 255) g_blocksum[blockIdx.x] = s[255];
}

// ---------------- scan pass 2: each block computes its own prefix of blocksums ----------------
__global__ void scan_add_kernel() {
    __shared__ int sred[256];
    int bid = blockIdx.x;
    int t = threadIdx.x;
    int v = 0;
    if (t < bid) v += g_blocksum[t];
    if (t + 256 < bid) v += g_blocksum[t + 256];
    sred[t] = v;
    __syncthreads();
    for (int d = 128; d > 0; d >>= 1) {
        if (t < d) sred[t] += sred[t + d];
        __syncthreads();
    }
    int base = sred[0];

    int i = bid * 256 + t;
    if (i >= N_NODES) return;
    int o = g_off[i] + base;
    g_off[i] = o;
    g_cursor[i] = o;
}

// ---------------- CSR fill (4 edges/thread, int4 loads) ----------------
__global__ void fill_kernel(const int* __restrict__ ei) {
    int e = blockIdx.x * blockDim.x + threadIdx.x;
    if (e >= N_EDGES / 4) return;
    int4 ss = ((const int4*)ei)[e];
    int4 dd = ((const int4*)(ei + N_EDGES))[e];
    g_csr[atomicAdd(&g_cursor[dd.x], 1)] = ss.x;
    g_csr[atomicAdd(&g_cursor[dd.y], 1)] = ss.y;
    g_csr[atomicAdd(&g_cursor[dd.z], 1)] = ss.z;
    g_csr[atomicAdd(&g_cursor[dd.w], 1)] = ss.w;
}

// ---------------- wmma GEMM; epilogue quantizes row to int8 + per-row scale ----------------
// LAYER1: A = g_xh, W = g_w1h -> g_q1/g_s1 (scale WITHOUT dis; folded later)
// else  : A = g_bufH, W = g_w2h -> g_q2/g_s2 (scale includes dis)
template<int K, bool LAYER1>
__global__ void __launch_bounds__(128) gemm_wmma_kernel() {
    constexpr int ALD = K + 8;           // halves
    constexpr int WLD = 72;              // halves
    constexpr int RU  = K / 8;           // uint4 per A row
    constexpr int A_BYTES   = 64 * ALD * 2;
    constexpr int OUT_BYTES = 64 * 64 * 4;
    constexpr int R1 = (A_BYTES > OUT_BYTES) ? A_BYTES : OUT_BYTES;
    __shared__ char s_mem[R1 + K * WLD * 2];

    __half* sA   = (__half*)s_mem;
    float*  sOut = (float*)s_mem;                 // aliases sA (sync-separated)
    __half* sW   = (__half*)(s_mem + R1);

    int tid = threadIdx.x;
    int block0 = blockIdx.x * 64;

    const uint4* wsrc = (const uint4*)(LAYER1 ? g_w1h : g_w2h);
    for (int j = tid; j < K * 64 / 8; j += 128) {
        int r = j >> 3, c8 = j & 7;
        *(uint4*)(sW + r * WLD + c8 * 8) = wsrc[j];
    }

    const uint4* asrc = LAYER1 ? g_xh : g_bufH;
    for (int j = tid; j < 64 * RU; j += 128) {
        int r = j / RU, u = j % RU;
        int gr = block0 + r; if (gr >= N_NODES) gr = N_NODES - 1;
        *(uint4*)(sA + r * ALD + u * 8) = asrc[(size_t)gr * RU + u];
    }
    __syncthreads();

    int warp = tid >> 5;
    int wrow = warp * 16;

    wmma::fragment<wmma::accumulator, 16, 16, 16, float> acc[4];
#pragma unroll
    for (int n = 0; n < 4; ++n) wmma::fill_fragment(acc[n], 0.0f);

    wmma::fragment<wmma::matrix_a, 16, 16, 16, __half, wmma::row_major> fa;
    wmma::fragment<wmma::matrix_b, 16, 16, 16, __half, wmma::row_major> fb;
#pragma unroll
    for (int kf = 0; kf < K / 16; ++kf) {
        wmma::load_matrix_sync(fa, sA + wrow * ALD + kf * 16, ALD);
#pragma unroll
        for (int n = 0; n < 4; ++n) {
            wmma::load_matrix_sync(fb, sW + kf * 16 * WLD + n * 16, WLD);
            wmma::mma_sync(acc[n], fa, fb, acc[n]);
        }
    }

    __syncthreads();
#pragma unroll
    for (int n = 0; n < 4; ++n)
        wmma::store_matrix_sync(sOut + wrow * 64 + n * 16, acc[n], 64, wmma::mem_row_major);
    __syncthreads();

    // epilogue: per-row absmax -> int8 quantize. 2 threads per row.
    int r  = tid >> 1;
    int hf = tid & 1;
    int gr = block0 + r;
    const float* row = sOut + r * 64 + hf * 32;

    float m = 0.0f;
#pragma unroll
    for (int q = 0; q < 32; ++q) m = fmaxf(m, fabsf(row[q]));
    m = fmaxf(m, __shfl_xor_sync(0xFFFFFFFFu, m, 1));   // pair-reduce (uniform exec)
    float inv = (m > 0.0f) ? 127.0f / m : 0.0f;

    if (gr < N_NODES) {
        if (hf == 0) {
            float sc = m * (1.0f / 127.0f);
            if (!LAYER1) sc *= g_dis[gr];
            (LAYER1 ? g_s1 : g_s2)[gr] = sc;
        }
        unsigned int ow[8];
#pragma unroll
        for (int q = 0; q < 8; ++q) {
            int b0 = __float2int_rn(row[q*4 + 0] * inv);
            int b1_ = __float2int_rn(row[q*4 + 1] * inv);
            int b2_ = __float2int_rn(row[q*4 + 2] * inv);
            int b3_ = __float2int_rn(row[q*4 + 3] * inv);
            ow[q] = (unsigned int)(b0 & 0xFF) | ((unsigned int)(b1_ & 0xFF) << 8)
                  | ((unsigned int)(b2_ & 0xFF) << 16) | ((unsigned int)b3_ << 24);
        }
        uint4* dst = LAYER1 ? g_q1 : g_q2;
        dst[gr * 4 + hf * 2 + 0] = make_uint4(ow[0], ow[1], ow[2], ow[3]);
        dst[gr * 4 + hf * 2 + 1] = make_uint4(ow[4], ow[5], ow[6], ow[7]);
    }
}

// ---------------- gather (int8 rows, per-row scale) ----------------
// decode 8 int8 from uint2 via char4 (guaranteed sign extension), acc += s * val
__device__ __forceinline__ void acc_q8(float* acc, uint2 v, float s) {
    union { unsigned int u; char4 c; } a, b;
    a.u = v.x; b.u = v.y;
    acc[0] += (float)a.c.x * s;
    acc[1] += (float)a.c.y * s;
    acc[2] += (float)a.c.z * s;
    acc[3] += (float)a.c.w * s;
    acc[4] += (float)b.c.x * s;
    acc[5] += (float)b.c.y * s;
    acc[6] += (float)b.c.z * s;
    acc[7] += (float)b.c.w * s;
}

// MODE 1: src g_q1/g_s1 (dis-folded); out = fp16(relu(acc*dn + b1)) -> g_bufH
// MODE 2: src g_q2/g_s2 (dis-folded); pooled[batch[n]] += acc*dn (fused pooling)
template<int MODE>
__global__ void __launch_bounds__(256) gather_kernel(const float* __restrict__ b1,
                                                     const int* __restrict__ batch) {
    int t = blockIdx.x * 256 + threadIdx.x;
    int n = t >> 3;                 // 8 threads/node; grid covers exactly N_NODES*8
    int lane = t & 7;

    const uint2*  src = (const uint2*)(MODE == 1 ? g_q1 : g_q2);
    const float*  scl = (MODE == 1 ? g_s1 : g_s2);

    int st  = g_off[n];
    int deg = g_indeg[n];
    float dn = g_dis[n];

    float acc[8];
#pragma unroll
    for (int p = 0; p < 8; ++p) acc[p] = 0.0f;
    acc_q8(acc, src[(size_t)n * 8 + lane], scl[n]);   // self loop

    int j = 0;
    for (; j + 8 <= deg; j += 8) {
        int sidx[8];
#pragma unroll
        for (int i = 0; i < 8; ++i) sidx[i] = g_csr[st + j + i];
        uint2 v[8];
#pragma unroll
        for (int i = 0; i < 8; ++i) v[i] = src[(size_t)sidx[i] * 8 + lane];
        float ds[8];
#pragma unroll
        for (int i = 0; i < 8; ++i) ds[i] = scl[sidx[i]];
#pragma unroll
        for (int i = 0; i < 8; ++i) acc_q8(acc, v[i], ds[i]);
    }
    for (; j < deg; ++j) {
        int s = g_csr[st + j];
        acc_q8(acc, src[(size_t)s * 8 + lane], scl[s]);
    }

    if (MODE == 1) {
        union { uint4 u; __half2 h[4]; } pk;
#pragma unroll
        for (int p = 0; p < 4; ++p) {
            float v0 = fmaxf(acc[p*2]     * dn + b1[lane*8 + p*2],     0.0f);
            float v1 = fmaxf(acc[p*2 + 1] * dn + b1[lane*8 + p*2 + 1], 0.0f);
            pk.h[p] = __float22half2_rn(make_float2(v0, v1));
        }
        g_bufH[(size_t)n * 8 + lane] = pk.u;
    } else {
#pragma unroll
        for (int p = 0; p < 8; ++p) acc[p] *= dn;
        int g = batch[n];
        unsigned eq = __match_any_sync(0xFFFFFFFFu, g);
        if (eq == 0xFFFFFFFFu) {
#pragma unroll
            for (int p = 0; p < 8; ++p) {
                acc[p] += __shfl_xor_sync(0xFFFFFFFFu, acc[p], 8);
                acc[p] += __shfl_xor_sync(0xFFFFFFFFu, acc[p], 16);
            }
            if ((threadIdx.x & 31) < 8) {
#pragma unroll
                for (int p = 0; p < 8; ++p)
                    atomicAdd(&g_pooled[g * HID + lane * 8 + p], acc[p]);
            }
        } else {
#pragma unroll
            for (int p = 0; p < 8; ++p)
                atomicAdd(&g_pooled[g * HID + lane * 8 + p], acc[p]);
        }
    }
}

// ---------------- head: mean + b2, fc1(relu), fc2 -> out ----------------
__global__ void __launch_bounds__(64) head_kernel(const int* __restrict__ batch,
                                                  const float* __restrict__ b2,
                                                  const float* __restrict__ Wf1,
                                                  const float* __restrict__ bf1,
                                                  const float* __restrict__ Wf2,
                                                  const float* __restrict__ bf2,
                                                  float* __restrict__ out) {
    __shared__ int   s_bound[2];
    __shared__ float s_mean[HID];
    __shared__ float s_h1[32];

    int g = blockIdx.x;
    int c = threadIdx.x;

    if (c < 2) {
        int target = g + c;
        int lo = 0, hi = N_NODES;
        while (lo < hi) {
            int mid = (lo + hi) >> 1;
            if (batch[mid] < target) lo = mid + 1; else hi = mid;
        }
        s_bound[c] = lo;
    }
    __syncthreads();

    int cnt = s_bound[1] - s_bound[0];
    float invc = (cnt > 0) ? (1.0f / (float)cnt) : 0.0f;
    s_mean[c] = (cnt > 0) ? (g_pooled[g * HID + c] * invc + b2[c]) : 0.0f;
    __syncthreads();

    if (c < 32) {
        float h1 = bf1[c];
#pragma unroll
        for (int k = 0; k < HID; ++k) h1 += s_mean[k] * Wf1[k * 32 + c];
        s_h1[c] = fmaxf(h1, 0.0f);
    }
    __syncthreads();

    if (c < N_CLASSES) {
        float o = bf2[c];
#pragma unroll
        for (int k = 0; k < 32; ++k) o += s_h1[k] * Wf2[k * N_CLASSES + c];
        out[g * N_CLASSES + c] = o;
    }
}

// ---------------- launch ----------------
extern "C" void kernel_launch(void* const* d_in, const int* in_sizes, int n_in,
                              void* d_out, int out_size) {
    const float* x   = (const float*)d_in[0];
    const int*   ei  = (const int*)d_in[1];     // int32 (JAX x64 disabled)
    const int*   bat = (const int*)d_in[2];     // int32
    const float* W1  = (const float*)d_in[3];
    const float* b1  = (const float*)d_in[4];
    const float* W2  = (const float*)d_in[5];
    const float* b2  = (const float*)d_in[6];
    const float* Wf1 = (const float*)d_in[7];
    const float* bf1 = (const float*)d_in[8];
    const float* Wf2 = (const float*)d_in[9];
    const float* bf2 = (const float*)d_in[10];
    float* out = (float*)d_out;

    const int TB  = 256;
    const int gN  = (N_NODES + TB - 1) / TB;            // 391
    const int gE4 = (N_EDGES / 4 + TB - 1) / TB;        // 3125
    const int gW  = (N_NODES + 63) / 64;                // 1563
    const int gX  = (N_NODES * 16 + TB - 1) / TB;       // 6250
    const int gG  = (N_NODES * 8) / TB;                 // 3125 exact

    // fork/join resources (created per call, not destroyed during capture; no dev mem)
    cudaStream_t sB;
    cudaEvent_t evStart, evScan, evJoin;
    cudaStreamCreateWithFlags(&sB, cudaStreamNonBlocking);
    cudaEventCreateWithFlags(&evStart, cudaEventDisableTiming);
    cudaEventCreateWithFlags(&evScan,  cudaEventDisableTiming);
    cudaEventCreateWithFlags(&evJoin,  cudaEventDisableTiming);

    // stream B from t=0: x/W conversion + GEMM1 (graph-independent)
    cudaEventRecord(evStart, 0);
    cudaStreamWaitEvent(sB, evStart, 0);
    convw_kernel<<<(F_IN * HID + TB - 1) / TB, TB, 0, sB>>>(W1, W2);
    xhalf_kernel<<<gX, TB, 0, sB>>>(x);
    gemm_wmma_kernel<F_IN, true><<<gW, 128, 0, sB>>>();

    // main: CSR build (dis fused into scan_local)
    zinit_kernel<<<gN, TB>>>();
    hist_kernel<<<gE4, TB>>>(ei);
    scan_local_kernel<<<gN, TB>>>();
    cudaEventRecord(evScan, 0);
    scan_add_kernel<<<gN, TB>>>();
    fill_kernel<<<gE4, TB>>>(ei);

    // stream B: fold dis into layer-1 scales (needs scan_local's dis + gemm1's s1)
    cudaStreamWaitEvent(sB, evScan, 0);
    foldscale_kernel<<<gN, TB, 0, sB>>>();
    cudaEventRecord(evJoin, sB);

    cudaStreamWaitEvent(0, evJoin, 0);

    // layer 1 aggregate (int8 rows; fused relu(+b1), fp16 out)
    gather_kernel<1><<<gG, TB>>>(b1, bat);

    // layer 2
    gemm_wmma_kernel<HID, false><<<gW, 128>>>();
    gather_kernel<2><<<gG, TB>>>(b1, bat);   // fused pooling

    // head
    head_kernel<<<N_GRAPHS, 64>>>(bat, b2, Wf1, bf1, Wf2, bf2, out);
}

// round 15
// speedup vs baseline: 1.1279x; 1.1279x over previous
#include <cuda_runtime.h>
#include <cuda_fp16.h>
#include <mma.h>

using namespace nvcuda;

#define N_NODES   100000
#define N_EDGES   3200000
#define F_IN      128
#define HID       64
#define N_GRAPHS  256
#define N_CLASSES 8
#define NB        391            // ceil(N_NODES / 256)
#define DBINS     256

// ---------------- scratch (static device globals; no runtime allocs) ----------------
__device__ int    g_indeg[N_NODES];
__device__ int    g_off[N_NODES];
__device__ int    g_cursor[N_NODES];
__device__ int    g_blocksum[NB];
__device__ float  g_dis[N_NODES];
__device__ int    g_csr[N_EDGES];
__device__ int    g_dhist[DBINS];
__device__ int    g_dcur[DBINS];
__device__ int    g_perm[N_NODES];                // nodes sorted by degree (gather1 order)
__device__ uint4  g_xh[(size_t)N_NODES * 16];     // fp16 x (128 halves/node)
__device__ __half g_w1h[F_IN * HID];
__device__ __half g_w2h[HID * HID];
__device__ uint4  g_bufAh[(size_t)N_NODES * 8];   // fp16 gemm1 out, raw (dis applied in gather1)
__device__ uint4  g_bufA2h[(size_t)N_NODES * 8];  // fp16 gemm2 out, scaled by dis (gather2 src)
__device__ uint4  g_bufH[(size_t)N_NODES * 8];    // fp16 relu(gather1 + b1)  (gemm2 input)
__device__ float  g_pooled[N_GRAPHS * HID];       // fused pooling accumulator

// ---------------- stream-B prepass: W -> fp16 ----------------
__global__ void convw_kernel(const float* __restrict__ W1, const float* __restrict__ W2) {
    int i = blockIdx.x * blockDim.x + threadIdx.x;
    if (i < F_IN * HID) g_w1h[i] = __float2half(W1[i]);
    if (i < HID * HID) g_w2h[i] = __float2half(W2[i]);
}

// ---------------- stream-B prepass: x -> fp16 (8 floats/thread) ----------------
__global__ void xhalf_kernel(const float* __restrict__ x) {
    int i = blockIdx.x * blockDim.x + threadIdx.x;   // over N_NODES*16
    if (i >= N_NODES * 16) return;
    float4 a = ((const float4*)x)[(size_t)i * 2];
    float4 b = ((const float4*)x)[(size_t)i * 2 + 1];
    union { uint4 u; __half2 h[4]; } pk;
    pk.h[0] = __float22half2_rn(make_float2(a.x, a.y));
    pk.h[1] = __float22half2_rn(make_float2(a.z, a.w));
    pk.h[2] = __float22half2_rn(make_float2(b.x, b.y));
    pk.h[3] = __float22half2_rn(make_float2(b.z, b.w));
    g_xh[i] = pk.u;
}

// ---------------- init: zero indeg + pooled + degree-hist ----------------
__global__ void zinit_kernel() {
    int i = blockIdx.x * blockDim.x + threadIdx.x;
    if (i < N_NODES) g_indeg[i] = 0;
    if (i < N_GRAPHS * HID) g_pooled[i] = 0.0f;
    if (i < DBINS) g_dhist[i] = 0;
}

// ---------------- in-degree histogram over dst (4 edges/thread, int4 loads) ----------------
__global__ void hist_kernel(const int* __restrict__ ei) {
    int e = blockIdx.x * blockDim.x + threadIdx.x;
    if (e >= N_EDGES / 4) return;
    int4 dd = ((const int4*)(ei + N_EDGES))[e];
    atomicAdd(&g_indeg[dd.x], 1);
    atomicAdd(&g_indeg[dd.y], 1);
    atomicAdd(&g_indeg[dd.z], 1);
    atomicAdd(&g_indeg[dd.w], 1);
}

// ---------------- dis = rsqrt(indeg + 1) ----------------
__global__ void dis_kernel() {
    int i = blockIdx.x * blockDim.x + threadIdx.x;
    if (i < N_NODES) g_dis[i] = rsqrtf((float)(g_indeg[i] + 1));
}

// ---------------- degree-sort permutation (stream B, off critical path) ----------------
__global__ void dhist_kernel() {
    __shared__ int sh[DBINS];
    int t = threadIdx.x;
    sh[t] = 0;
    __syncthreads();
    int i = blockIdx.x * 256 + t;
    if (i < N_NODES) {
        int d = g_indeg[i]; if (d > 255) d = 255;
        atomicAdd(&sh[d], 1);
    }
    __syncthreads();
    if (sh[t] > 0) atomicAdd(&g_dhist[t], sh[t]);
}

__global__ void dscan_kernel() {
    __shared__ int s[DBINS];
    int i = threadIdx.x;
    int v = g_dhist[i];
    s[i] = v;
    __syncthreads();
    for (int d = 1; d < DBINS; d <<= 1) {
        int t = (i >= d) ? s[i - d] : 0;
        __syncthreads();
        s[i] += t;
        __syncthreads();
    }
    g_dcur[i] = s[i] - v;   // exclusive
}

__global__ void dperm_kernel() {
    int i = blockIdx.x * blockDim.x + threadIdx.x;
    if (i >= N_NODES) return;
    int d = g_indeg[i]; if (d > 255) d = 255;
    int pos = atomicAdd(&g_dcur[d], 1);
    g_perm[pos] = i;
}

// ---------------- scan pass 1: per-block exclusive scan + block sums ----------------
__global__ void scan_local_kernel() {
    __shared__ int s[256];
    int i = blockIdx.x * 256 + threadIdx.x;
    int v = (i < N_NODES) ? g_indeg[i] : 0;
    s[threadIdx.x] = v;
    __syncthreads();
    for (int d = 1; d < 256; d <<= 1) {
        int t = (threadIdx.x >= d) ? s[threadIdx.x - d] : 0;
        __syncthreads();
        s[threadIdx.x] += t;
        __syncthreads();
    }
    if (i < N_NODES) g_off[i] = s[threadIdx.x] - v;
    if (threadIdx.x == 255) g_blocksum[blockIdx.x] = s[255];
}

__global__ void scan_sums_kernel() {
    __shared__ int s[512];
    int i = threadIdx.x;
    int v = (i < NB) ? g_blocksum[i] : 0;
    s[i] = v;
    __syncthreads();
    for (int d = 1; d < 512; d <<= 1) {
        int t = (i >= d) ? s[i - d] : 0;
        __syncthreads();
        s[i] += t;
        __syncthreads();
    }
    if (i < NB) g_blocksum[i] = s[i] - v;
}

__global__ void scan_add_kernel() {
    int i = blockIdx.x * 256 + threadIdx.x;
    if (i >= N_NODES) return;
    int o = g_off[i] + g_blocksum[blockIdx.x];
    g_off[i] = o;
    g_cursor[i] = o;
}

// ---------------- CSR fill (4 edges/thread, int4 loads) ----------------
__global__ void fill_kernel(const int* __restrict__ ei) {
    int e = blockIdx.x * blockDim.x + threadIdx.x;
    if (e >= N_EDGES / 4) return;
    int4 ss = ((const int4*)ei)[e];
    int4 dd = ((const int4*)(ei + N_EDGES))[e];
    g_csr[atomicAdd(&g_cursor[dd.x], 1)] = ss.x;
    g_csr[atomicAdd(&g_cursor[dd.y], 1)] = ss.y;
    g_csr[atomicAdd(&g_cursor[dd.z], 1)] = ss.z;
    g_csr[atomicAdd(&g_cursor[dd.w], 1)] = ss.w;
}

// ---------------- wmma GEMM (all-fp16 inputs, vector loads) ----------------
// LAYER1: A = g_xh, W = g_w1h, out = g_bufAh raw (dis applied in gather1)
// else  : A = g_bufH, W = g_w2h, out = g_bufA2h scaled by dis
template<int K, bool LAYER1>
__global__ void __launch_bounds__(128) gemm_wmma_kernel() {
    constexpr int ALD = K + 8;           // halves
    constexpr int WLD = 72;              // halves
    constexpr int RU  = K / 8;           // uint4 per A row
    constexpr int A_BYTES   = 64 * ALD * 2;
    constexpr int OUT_BYTES = 64 * 64 * 4;
    constexpr int R1 = (A_BYTES > OUT_BYTES) ? A_BYTES : OUT_BYTES;
    __shared__ char s_mem[R1 + K * WLD * 2];

    __half* sA   = (__half*)s_mem;
    float*  sOut = (float*)s_mem;                 // aliases sA (sync-separated)
    __half* sW   = (__half*)(s_mem + R1);

    int tid = threadIdx.x;
    int block0 = blockIdx.x * 64;

    const uint4* wsrc = (const uint4*)(LAYER1 ? g_w1h : g_w2h);
    for (int j = tid; j < K * 64 / 8; j += 128) {
        int r = j >> 3, c8 = j & 7;
        *(uint4*)(sW + r * WLD + c8 * 8) = wsrc[j];
    }

    const uint4* asrc = LAYER1 ? g_xh : g_bufH;
    for (int j = tid; j < 64 * RU; j += 128) {
        int r = j / RU, u = j % RU;
        int gr = block0 + r; if (gr >= N_NODES) gr = N_NODES - 1;
        *(uint4*)(sA + r * ALD + u * 8) = asrc[(size_t)gr * RU + u];
    }
    __syncthreads();

    int warp = tid >> 5;
    int wrow = warp * 16;

    wmma::fragment<wmma::accumulator, 16, 16, 16, float> acc[4];
#pragma unroll
    for (int n = 0; n < 4; ++n) wmma::fill_fragment(acc[n], 0.0f);

    wmma::fragment<wmma::matrix_a, 16, 16, 16, __half, wmma::row_major> fa;
    wmma::fragment<wmma::matrix_b, 16, 16, 16, __half, wmma::row_major> fb;
#pragma unroll
    for (int kf = 0; kf < K / 16; ++kf) {
        wmma::load_matrix_sync(fa, sA + wrow * ALD + kf * 16, ALD);
#pragma unroll
        for (int n = 0; n < 4; ++n) {
            wmma::load_matrix_sync(fb, sW + kf * 16 * WLD + n * 16, WLD);
            wmma::mma_sync(acc[n], fa, fb, acc[n]);
        }
    }

    __syncthreads();
#pragma unroll
    for (int n = 0; n < 4; ++n)
        wmma::store_matrix_sync(sOut + wrow * 64 + n * 16, acc[n], 64, wmma::mem_row_major);
    __syncthreads();

    int r  = tid >> 1;
    int hf = tid & 1;
    int gr = block0 + r;
    if (gr < N_NODES) {
        float s = LAYER1 ? 1.0f : g_dis[gr];
        const float* row = sOut + r * 64 + hf * 32;
        union { uint4 u; __half2 h[4]; } pk;
#pragma unroll
        for (int q = 0; q < 4; ++q) {
#pragma unroll
            for (int p = 0; p < 4; ++p)
                pk.h[p] = __float22half2_rn(make_float2(row[q*8 + p*2] * s, row[q*8 + p*2 + 1] * s));
            uint4* dst = LAYER1 ? g_bufAh : g_bufA2h;
            dst[(size_t)gr * 8 + hf * 4 + q] = pk.u;
        }
    }
}

// ---------------- gather ----------------
__device__ __forceinline__ void acc_row(float* acc, uint4 v) {
    union { uint4 u; __half2 h[4]; } pk; pk.u = v;
#pragma unroll
    for (int p = 0; p < 4; ++p) {
        float2 f = __half22float2(pk.h[p]);
        acc[p * 2]     += f.x;
        acc[p * 2 + 1] += f.y;
    }
}
__device__ __forceinline__ void acc_row_fma(float* acc, uint4 v, float s) {
    union { uint4 u; __half2 h[4]; } pk; pk.u = v;
#pragma unroll
    for (int p = 0; p < 4; ++p) {
        float2 f = __half22float2(pk.h[p]);
        acc[p * 2]     += f.x * s;
        acc[p * 2 + 1] += f.y * s;
    }
}

// MODE 1: nodes in degree-sorted order (g_perm); src g_bufAh raw -> acc += dis[s]*row[s];
//         out = fp16(relu(acc*dn + b1)) -> g_bufH
// MODE 2: sequential nodes; src g_bufA2h pre-scaled -> plain adds;
//         pooled[batch[n]] += acc*dn (fused pooling, sorted-batch warp reduction)
template<int MODE>
__global__ void __launch_bounds__(256) gather_kernel(const float* __restrict__ b1,
                                                     const int* __restrict__ batch) {
    int t = blockIdx.x * 256 + threadIdx.x;
    int n = (MODE == 1) ? g_perm[t >> 3] : (t >> 3);  // 8 threads/node
    int lane = t & 7;

    const uint4* src = (MODE == 1) ? g_bufAh : g_bufA2h;

    int st  = g_off[n];
    int deg = g_indeg[n];
    float dn = g_dis[n];

    float acc[8];
#pragma unroll
    for (int p = 0; p < 8; ++p) acc[p] = 0.0f;
    // self loop
    if (MODE == 1) acc_row_fma(acc, src[(size_t)n * 8 + lane], dn);
    else           acc_row(acc, src[(size_t)n * 8 + lane]);

    int j = 0;
    for (; j + 8 <= deg; j += 8) {
        int sidx[8];
#pragma unroll
        for (int i = 0; i < 8; ++i) sidx[i] = g_csr[st + j + i];
        uint4 v[8];
#pragma unroll
        for (int i = 0; i < 8; ++i) v[i] = src[(size_t)sidx[i] * 8 + lane];
        if (MODE == 1) {
            float ds[8];
#pragma unroll
            for (int i = 0; i < 8; ++i) ds[i] = g_dis[sidx[i]];
#pragma unroll
            for (int i = 0; i < 8; ++i) acc_row_fma(acc, v[i], ds[i]);
        } else {
#pragma unroll
            for (int i = 0; i < 8; ++i) acc_row(acc, v[i]);
        }
    }
    for (; j < deg; ++j) {
        int s = g_csr[st + j];
        if (MODE == 1) acc_row_fma(acc, src[(size_t)s * 8 + lane], g_dis[s]);
        else           acc_row(acc, src[(size_t)s * 8 + lane]);
    }

    if (MODE == 1) {
        union { uint4 u; __half2 h[4]; } pk;
#pragma unroll
        for (int p = 0; p < 4; ++p) {
            float v0 = fmaxf(acc[p*2]     * dn + b1[lane*8 + p*2],     0.0f);
            float v1 = fmaxf(acc[p*2 + 1] * dn + b1[lane*8 + p*2 + 1], 0.0f);
            pk.h[p] = __float22half2_rn(make_float2(v0, v1));
        }
        g_bufH[(size_t)n * 8 + lane] = pk.u;
    } else {
#pragma unroll
        for (int p = 0; p < 8; ++p) acc[p] *= dn;
        int g = batch[n];
        unsigned eq = __match_any_sync(0xFFFFFFFFu, g);
        if (eq == 0xFFFFFFFFu) {
#pragma unroll
            for (int p = 0; p < 8; ++p) {
                acc[p] += __shfl_xor_sync(0xFFFFFFFFu, acc[p], 8);
                acc[p] += __shfl_xor_sync(0xFFFFFFFFu, acc[p], 16);
            }
            if ((threadIdx.x & 31) < 8) {
#pragma unroll
                for (int p = 0; p < 8; ++p)
                    atomicAdd(&g_pooled[g * HID + lane * 8 + p], acc[p]);
            }
        } else {
#pragma unroll
            for (int p = 0; p < 8; ++p)
                atomicAdd(&g_pooled[g * HID + lane * 8 + p], acc[p]);
        }
    }
}

// ---------------- head: mean + b2, fc1(relu), fc2 -> out ----------------
__global__ void __launch_bounds__(64) head_kernel(const int* __restrict__ batch,
                                                  const float* __restrict__ b2,
                                                  const float* __restrict__ Wf1,
                                                  const float* __restrict__ bf1,
                                                  const float* __restrict__ Wf2,
                                                  const float* __restrict__ bf2,
                                                  float* __restrict__ out) {
    __shared__ int   s_bound[2];
    __shared__ float s_mean[HID];
    __shared__ float s_h1[32];

    int g = blockIdx.x;
    int c = threadIdx.x;

    if (c < 2) {
        int target = g + c;
        int lo = 0, hi = N_NODES;
        while (lo < hi) {
            int mid = (lo + hi) >> 1;
            if (batch[mid] < target) lo = mid + 1; else hi = mid;
        }
        s_bound[c] = lo;
    }
    __syncthreads();

    int cnt = s_bound[1] - s_bound[0];
    float invc = (cnt > 0) ? (1.0f / (float)cnt) : 0.0f;
    s_mean[c] = (cnt > 0) ? (g_pooled[g * HID + c] * invc + b2[c]) : 0.0f;
    __syncthreads();

    if (c < 32) {
        float h1 = bf1[c];
#pragma unroll
        for (int k = 0; k < HID; ++k) h1 += s_mean[k] * Wf1[k * 32 + c];
        s_h1[c] = fmaxf(h1, 0.0f);
    }
    __syncthreads();

    if (c < N_CLASSES) {
        float o = bf2[c];
#pragma unroll
        for (int k = 0; k < 32; ++k) o += s_h1[k] * Wf2[k * N_CLASSES + c];
        out[g * N_CLASSES + c] = o;
    }
}

// ---------------- launch ----------------
extern "C" void kernel_launch(void* const* d_in, const int* in_sizes, int n_in,
                              void* d_out, int out_size) {
    const float* x   = (const float*)d_in[0];
    const int*   ei  = (const int*)d_in[1];     // int32 (JAX x64 disabled)
    const int*   bat = (const int*)d_in[2];     // int32
    const float* W1  = (const float*)d_in[3];
    const float* b1  = (const float*)d_in[4];
    const float* W2  = (const float*)d_in[5];
    const float* b2  = (const float*)d_in[6];
    const float* Wf1 = (const float*)d_in[7];
    const float* bf1 = (const float*)d_in[8];
    const float* Wf2 = (const float*)d_in[9];
    const float* bf2 = (const float*)d_in[10];
    float* out = (float*)d_out;

    const int TB  = 256;
    const int gN  = (N_NODES + TB - 1) / TB;            // 391
    const int gE4 = (N_EDGES / 4 + TB - 1) / TB;        // 3125
    const int gW  = (N_NODES + 63) / 64;                // 1563
    const int gX  = (N_NODES * 16 + TB - 1) / TB;       // 6250
    const int gG  = (N_NODES * 8) / TB;                 // 3125 exact

    // fork/join resources (created per call, not destroyed during capture; no dev mem)
    cudaStream_t sB;
    cudaEvent_t evStart, evHist, evJoin;
    cudaStreamCreateWithFlags(&sB, cudaStreamNonBlocking);
    cudaEventCreateWithFlags(&evStart, cudaEventDisableTiming);
    cudaEventCreateWithFlags(&evHist,  cudaEventDisableTiming);
    cudaEventCreateWithFlags(&evJoin,  cudaEventDisableTiming);

    // stream B from t=0: x/W conversion + GEMM1 (graph-independent, raw output)
    cudaEventRecord(evStart, 0);
    cudaStreamWaitEvent(sB, evStart, 0);
    convw_kernel<<<(F_IN * HID + TB - 1) / TB, TB, 0, sB>>>(W1, W2);
    xhalf_kernel<<<gX, TB, 0, sB>>>(x);
    gemm_wmma_kernel<F_IN, true><<<gW, 128, 0, sB>>>();

    // main: CSR build
    zinit_kernel<<<gN, TB>>>();
    hist_kernel<<<gE4, TB>>>(ei);
    cudaEventRecord(evHist, 0);
    dis_kernel<<<gN, TB>>>();
    scan_local_kernel<<<gN, TB>>>();
    scan_sums_kernel<<<1, 512>>>();
    scan_add_kernel<<<gN, TB>>>();
    fill_kernel<<<gE4, TB>>>(ei);

    // stream B: degree-sort permutation (needs indeg only), in GEMM1's slack
    cudaStreamWaitEvent(sB, evHist, 0);
    dhist_kernel<<<gN, DBINS, 0, sB>>>();
    dscan_kernel<<<1, DBINS, 0, sB>>>();
    dperm_kernel<<<gN, TB, 0, sB>>>();
    cudaEventRecord(evJoin, sB);

    cudaStreamWaitEvent(0, evJoin, 0);

    // layer 1 aggregate (degree-sorted, dis[s] FMA + fused relu(+b1), fp16 out)
    gather_kernel<1><<<gG, TB>>>(b1, bat);

    // layer 2
    gemm_wmma_kernel<HID, false><<<gW, 128>>>();
    gather_kernel<2><<<gG, TB>>>(b1, bat);   // sequential order, fused pooling

    // head
    head_kernel<<<N_GRAPHS, 64>>>(bat, b2, Wf1, bf1, Wf2, bf2, out);
}

// round 16
// speedup vs baseline: 1.2369x; 1.0966x over previous
#include <cuda_runtime.h>
#include <cuda_fp16.h>
#include <mma.h>

using namespace nvcuda;

#define N_NODES   100000
#define N_EDGES   3200000
#define F_IN      128
#define HID       64
#define N_GRAPHS  256
#define N_CLASSES 8
#define NB        391            // ceil(N_NODES / 256)

// ---------------- scratch (static device globals; no runtime allocs) ----------------
__device__ int    g_indeg[N_NODES];
__device__ int    g_off[N_NODES];
__device__ int    g_cursor[N_NODES];
__device__ int    g_blocksum[NB];
__device__ float  g_dis[N_NODES];
__device__ __half g_dish[N_NODES];                // fp16 dis (gather1 HFMA2 scale)
__device__ int    g_csr[N_EDGES];
__device__ uint4  g_xh[(size_t)N_NODES * 16];     // fp16 x (128 halves/node)
__device__ __half g_w1h[F_IN * HID];
__device__ __half g_w2h[HID * HID];
__device__ uint4  g_bufAh[(size_t)N_NODES * 8];   // fp16 gemm1 out, raw (dis applied in gather1)
__device__ uint4  g_bufA2h[(size_t)N_NODES * 8];  // fp16 gemm2 out, scaled by dis (gather2 src)
__device__ uint4  g_bufH[(size_t)N_NODES * 8];    // fp16 relu(gather1 + b1)  (gemm2 input)
__device__ float  g_pooled[N_GRAPHS * HID];       // fused pooling accumulator

// ---------------- stream-B prepass: W -> fp16 ----------------
__global__ void convw_kernel(const float* __restrict__ W1, const float* __restrict__ W2) {
    int i = blockIdx.x * blockDim.x + threadIdx.x;
    if (i < F_IN * HID) g_w1h[i] = __float2half(W1[i]);
    if (i < HID * HID) g_w2h[i] = __float2half(W2[i]);
}

// ---------------- stream-B prepass: x -> fp16 (8 floats/thread) ----------------
__global__ void xhalf_kernel(const float* __restrict__ x) {
    int i = blockIdx.x * blockDim.x + threadIdx.x;   // over N_NODES*16
    if (i >= N_NODES * 16) return;
    float4 a = ((const float4*)x)[(size_t)i * 2];
    float4 b = ((const float4*)x)[(size_t)i * 2 + 1];
    union { uint4 u; __half2 h[4]; } pk;
    pk.h[0] = __float22half2_rn(make_float2(a.x, a.y));
    pk.h[1] = __float22half2_rn(make_float2(a.z, a.w));
    pk.h[2] = __float22half2_rn(make_float2(b.x, b.y));
    pk.h[3] = __float22half2_rn(make_float2(b.z, b.w));
    g_xh[i] = pk.u;
}

// ---------------- init: zero indeg + pooled ----------------
__global__ void zinit_kernel() {
    int i = blockIdx.x * blockDim.x + threadIdx.x;
    if (i < N_NODES) g_indeg[i] = 0;
    if (i < N_GRAPHS * HID) g_pooled[i] = 0.0f;
}

// ---------------- in-degree histogram over dst (4 edges/thread, int4 loads) ----------------
__global__ void hist_kernel(const int* __restrict__ ei) {
    int e = blockIdx.x * blockDim.x + threadIdx.x;
    if (e >= N_EDGES / 4) return;
    int4 dd = ((const int4*)(ei + N_EDGES))[e];
    atomicAdd(&g_indeg[dd.x], 1);
    atomicAdd(&g_indeg[dd.y], 1);
    atomicAdd(&g_indeg[dd.z], 1);
    atomicAdd(&g_indeg[dd.w], 1);
}

// ---------------- dis = rsqrt(indeg + 1), fp32 + fp16 ----------------
__global__ void dis_kernel() {
    int i = blockIdx.x * blockDim.x + threadIdx.x;
    if (i < N_NODES) {
        float d = rsqrtf((float)(g_indeg[i] + 1));
        g_dis[i] = d;
        g_dish[i] = __float2half(d);
    }
}

// ---------------- scan pass 1: per-block exclusive scan + block sums ----------------
__global__ void scan_local_kernel() {
    __shared__ int s[256];
    int i = blockIdx.x * 256 + threadIdx.x;
    int v = (i < N_NODES) ? g_indeg[i] : 0;
    s[threadIdx.x] = v;
    __syncthreads();
    for (int d = 1; d < 256; d <<= 1) {
        int t = (threadIdx.x >= d) ? s[threadIdx.x - d] : 0;
        __syncthreads();
        s[threadIdx.x] += t;
        __syncthreads();
    }
    if (i < N_NODES) g_off[i] = s[threadIdx.x] - v;
    if (threadIdx.x == 255) g_blocksum[blockIdx.x] = s[255];
}

__global__ void scan_sums_kernel() {
    __shared__ int s[512];
    int i = threadIdx.x;
    int v = (i < NB) ? g_blocksum[i] : 0;
    s[i] = v;
    __syncthreads();
    for (int d = 1; d < 512; d <<= 1) {
        int t = (i >= d) ? s[i - d] : 0;
        __syncthreads();
        s[i] += t;
        __syncthreads();
    }
    if (i < NB) g_blocksum[i] = s[i] - v;
}

__global__ void scan_add_kernel() {
    int i = blockIdx.x * 256 + threadIdx.x;
    if (i >= N_NODES) return;
    int o = g_off[i] + g_blocksum[blockIdx.x];
    g_off[i] = o;
    g_cursor[i] = o;
}

// ---------------- CSR fill (4 edges/thread, int4 loads) ----------------
__global__ void fill_kernel(const int* __restrict__ ei) {
    int e = blockIdx.x * blockDim.x + threadIdx.x;
    if (e >= N_EDGES / 4) return;
    int4 ss = ((const int4*)ei)[e];
    int4 dd = ((const int4*)(ei + N_EDGES))[e];
    g_csr[atomicAdd(&g_cursor[dd.x], 1)] = ss.x;
    g_csr[atomicAdd(&g_cursor[dd.y], 1)] = ss.y;
    g_csr[atomicAdd(&g_cursor[dd.z], 1)] = ss.z;
    g_csr[atomicAdd(&g_cursor[dd.w], 1)] = ss.w;
}

// ---------------- wmma GEMM (all-fp16 inputs, vector loads) ----------------
// LAYER1: A = g_xh, W = g_w1h, out = g_bufAh raw (dis applied in gather1)
// else  : A = g_bufH, W = g_w2h, out = g_bufA2h scaled by dis
template<int K, bool LAYER1>
__global__ void __launch_bounds__(128) gemm_wmma_kernel() {
    constexpr int ALD = K + 8;           // halves
    constexpr int WLD = 72;              // halves
    constexpr int RU  = K / 8;           // uint4 per A row
    constexpr int A_BYTES   = 64 * ALD * 2;
    constexpr int OUT_BYTES = 64 * 64 * 4;
    constexpr int R1 = (A_BYTES > OUT_BYTES) ? A_BYTES : OUT_BYTES;
    __shared__ char s_mem[R1 + K * WLD * 2];

    __half* sA   = (__half*)s_mem;
    float*  sOut = (float*)s_mem;                 // aliases sA (sync-separated)
    __half* sW   = (__half*)(s_mem + R1);

    int tid = threadIdx.x;
    int block0 = blockIdx.x * 64;

    const uint4* wsrc = (const uint4*)(LAYER1 ? g_w1h : g_w2h);
    for (int j = tid; j < K * 64 / 8; j += 128) {
        int r = j >> 3, c8 = j & 7;
        *(uint4*)(sW + r * WLD + c8 * 8) = wsrc[j];
    }

    const uint4* asrc = LAYER1 ? g_xh : g_bufH;
    for (int j = tid; j < 64 * RU; j += 128) {
        int r = j / RU, u = j % RU;
        int gr = block0 + r; if (gr >= N_NODES) gr = N_NODES - 1;
        *(uint4*)(sA + r * ALD + u * 8) = asrc[(size_t)gr * RU + u];
    }
    __syncthreads();

    int warp = tid >> 5;
    int wrow = warp * 16;

    wmma::fragment<wmma::accumulator, 16, 16, 16, float> acc[4];
#pragma unroll
    for (int n = 0; n < 4; ++n) wmma::fill_fragment(acc[n], 0.0f);

    wmma::fragment<wmma::matrix_a, 16, 16, 16, __half, wmma::row_major> fa;
    wmma::fragment<wmma::matrix_b, 16, 16, 16, __half, wmma::row_major> fb;
#pragma unroll
    for (int kf = 0; kf < K / 16; ++kf) {
        wmma::load_matrix_sync(fa, sA + wrow * ALD + kf * 16, ALD);
#pragma unroll
        for (int n = 0; n < 4; ++n) {
            wmma::load_matrix_sync(fb, sW + kf * 16 * WLD + n * 16, WLD);
            wmma::mma_sync(acc[n], fa, fb, acc[n]);
        }
    }

    __syncthreads();
#pragma unroll
    for (int n = 0; n < 4; ++n)
        wmma::store_matrix_sync(sOut + wrow * 64 + n * 16, acc[n], 64, wmma::mem_row_major);
    __syncthreads();

    int r  = tid >> 1;
    int hf = tid & 1;
    int gr = block0 + r;
    if (gr < N_NODES) {
        float s = LAYER1 ? 1.0f : g_dis[gr];
        const float* row = sOut + r * 64 + hf * 32;
        union { uint4 u; __half2 h[4]; } pk;
#pragma unroll
        for (int q = 0; q < 4; ++q) {
#pragma unroll
            for (int p = 0; p < 4; ++p)
                pk.h[p] = __float22half2_rn(make_float2(row[q*8 + p*2] * s, row[q*8 + p*2 + 1] * s));
            uint4* dst = LAYER1 ? g_bufAh : g_bufA2h;
            dst[(size_t)gr * 8 + hf * 4 + q] = pk.u;
        }
    }
}

// ---------------- gather helpers ----------------
__device__ __forceinline__ void acc_row(float* acc, uint4 v) {
    union { uint4 u; __half2 h[4]; } pk; pk.u = v;
#pragma unroll
    for (int p = 0; p < 4; ++p) {
        float2 f = __half22float2(pk.h[p]);
        acc[p * 2]     += f.x;
        acc[p * 2 + 1] += f.y;
    }
}
__device__ __forceinline__ void acc_row_fma(float* acc, uint4 v, float s) {
    union { uint4 u; __half2 h[4]; } pk; pk.u = v;
#pragma unroll
    for (int p = 0; p < 4; ++p) {
        float2 f = __half22float2(pk.h[p]);
        acc[p * 2]     += f.x * s;
        acc[p * 2 + 1] += f.y * s;
    }
}
__device__ __forceinline__ void fold_h(float* acc, __half2* h) {
#pragma unroll
    for (int p = 0; p < 4; ++p) {
        float2 f = __half22float2(h[p]);
        acc[p * 2]     += f.x;
        acc[p * 2 + 1] += f.y;
        h[p] = __float2half2_rn(0.0f);
    }
}

// MODE 1: src g_bufAh raw -> hacc += dish[s]*row[s] (HFMA2), fp32 fold per 8-batch;
//         out = fp16(relu(acc*dn + b1)) -> g_bufH
// MODE 2: src g_bufA2h pre-scaled -> HADD2 accumulate, fp32 fold per 8-batch;
//         pooled[batch[n]] += acc*dn (fused pooling)
template<int MODE>
__global__ void __launch_bounds__(256) gather_kernel(const float* __restrict__ b1,
                                                     const int* __restrict__ batch) {
    int t = blockIdx.x * 256 + threadIdx.x;
    int n = t >> 3;                 // 8 threads/node; grid covers exactly N_NODES*8
    int lane = t & 7;

    const uint4* src = (MODE == 1) ? g_bufAh : g_bufA2h;

    int st  = g_off[n];
    int deg = g_indeg[n];
    float dn = g_dis[n];

    float acc[8];
#pragma unroll
    for (int p = 0; p < 8; ++p) acc[p] = 0.0f;
    // self loop in fp32
    if (MODE == 1) acc_row_fma(acc, src[(size_t)n * 8 + lane], dn);
    else           acc_row(acc, src[(size_t)n * 8 + lane]);

    __half2 h[4];
#pragma unroll
    for (int p = 0; p < 4; ++p) h[p] = __float2half2_rn(0.0f);

    int j = 0;
    for (; j + 8 <= deg; j += 8) {
        int sidx[8];
#pragma unroll
        for (int i = 0; i < 8; ++i) sidx[i] = g_csr[st + j + i];
        uint4 v[8];
#pragma unroll
        for (int i = 0; i < 8; ++i) v[i] = src[(size_t)sidx[i] * 8 + lane];
        if (MODE == 1) {
            __half2 s2[8];
#pragma unroll
            for (int i = 0; i < 8; ++i) s2[i] = __half2half2(g_dish[sidx[i]]);
#pragma unroll
            for (int i = 0; i < 8; ++i) {
                union { uint4 u; __half2 hh[4]; } pk; pk.u = v[i];
#pragma unroll
                for (int p = 0; p < 4; ++p) h[p] = __hfma2(pk.hh[p], s2[i], h[p]);
            }
        } else {
#pragma unroll
            for (int i = 0; i < 8; ++i) {
                union { uint4 u; __half2 hh[4]; } pk; pk.u = v[i];
#pragma unroll
                for (int p = 0; p < 4; ++p) h[p] = __hadd2(h[p], pk.hh[p]);
            }
        }
        fold_h(acc, h);   // fp32 master accumulate, reset hacc
    }
    for (; j < deg; ++j) {
        int s = g_csr[st + j];
        union { uint4 u; __half2 hh[4]; } pk; pk.u = src[(size_t)s * 8 + lane];
        if (MODE == 1) {
            __half2 s2 = __half2half2(g_dish[s]);
#pragma unroll
            for (int p = 0; p < 4; ++p) h[p] = __hfma2(pk.hh[p], s2, h[p]);
        } else {
#pragma unroll
            for (int p = 0; p < 4; ++p) h[p] = __hadd2(h[p], pk.hh[p]);
        }
    }
    // final fold (tail <8 terms)
#pragma unroll
    for (int p = 0; p < 4; ++p) {
        float2 f = __half22float2(h[p]);
        acc[p * 2]     += f.x;
        acc[p * 2 + 1] += f.y;
    }

    if (MODE == 1) {
        union { uint4 u; __half2 h[4]; } pk;
#pragma unroll
        for (int p = 0; p < 4; ++p) {
            float v0 = fmaxf(acc[p*2]     * dn + b1[lane*8 + p*2],     0.0f);
            float v1 = fmaxf(acc[p*2 + 1] * dn + b1[lane*8 + p*2 + 1], 0.0f);
            pk.h[p] = __float22half2_rn(make_float2(v0, v1));
        }
        g_bufH[(size_t)n * 8 + lane] = pk.u;
    } else {
#pragma unroll
        for (int p = 0; p < 8; ++p) acc[p] *= dn;
        int g = batch[n];
        unsigned eq = __match_any_sync(0xFFFFFFFFu, g);
        if (eq == 0xFFFFFFFFu) {
#pragma unroll
            for (int p = 0; p < 8; ++p) {
                acc[p] += __shfl_xor_sync(0xFFFFFFFFu, acc[p], 8);
                acc[p] += __shfl_xor_sync(0xFFFFFFFFu, acc[p], 16);
            }
            if ((threadIdx.x & 31) < 8) {
#pragma unroll
                for (int p = 0; p < 8; ++p)
                    atomicAdd(&g_pooled[g * HID + lane * 8 + p], acc[p]);
            }
        } else {
#pragma unroll
            for (int p = 0; p < 8; ++p)
                atomicAdd(&g_pooled[g * HID + lane * 8 + p], acc[p]);
        }
    }
}

// ---------------- head: mean + b2, fc1(relu), fc2 -> out ----------------
__global__ void __launch_bounds__(64) head_kernel(const int* __restrict__ batch,
                                                  const float* __restrict__ b2,
                                                  const float* __restrict__ Wf1,
                                                  const float* __restrict__ bf1,
                                                  const float* __restrict__ Wf2,
                                                  const float* __restrict__ bf2,
                                                  float* __restrict__ out) {
    __shared__ int   s_bound[2];
    __shared__ float s_mean[HID];
    __shared__ float s_h1[32];

    int g = blockIdx.x;
    int c = threadIdx.x;

    if (c < 2) {
        int target = g + c;
        int lo = 0, hi = N_NODES;
        while (lo < hi) {
            int mid = (lo + hi) >> 1;
            if (batch[mid] < target) lo = mid + 1; else hi = mid;
        }
        s_bound[c] = lo;
    }
    __syncthreads();

    int cnt = s_bound[1] - s_bound[0];
    float invc = (cnt > 0) ? (1.0f / (float)cnt) : 0.0f;
    s_mean[c] = (cnt > 0) ? (g_pooled[g * HID + c] * invc + b2[c]) : 0.0f;
    __syncthreads();

    if (c < 32) {
        float h1 = bf1[c];
#pragma unroll
        for (int k = 0; k < HID; ++k) h1 += s_mean[k] * Wf1[k * 32 + c];
        s_h1[c] = fmaxf(h1, 0.0f);
    }
    __syncthreads();

    if (c < N_CLASSES) {
        float o = bf2[c];
#pragma unroll
        for (int k = 0; k < 32; ++k) o += s_h1[k] * Wf2[k * N_CLASSES + c];
        out[g * N_CLASSES + c] = o;
    }
}

// ---------------- launch (round-10 structure) ----------------
extern "C" void kernel_launch(void* const* d_in, const int* in_sizes, int n_in,
                              void* d_out, int out_size) {
    const float* x   = (const float*)d_in[0];
    const int*   ei  = (const int*)d_in[1];     // int32 (JAX x64 disabled)
    const int*   bat = (const int*)d_in[2];     // int32
    const float* W1  = (const float*)d_in[3];
    const float* b1  = (const float*)d_in[4];
    const float* W2  = (const float*)d_in[5];
    const float* b2  = (const float*)d_in[6];
    const float* Wf1 = (const float*)d_in[7];
    const float* bf1 = (const float*)d_in[8];
    const float* Wf2 = (const float*)d_in[9];
    const float* bf2 = (const float*)d_in[10];
    float* out = (float*)d_out;

    const int TB  = 256;
    const int gN  = (N_NODES + TB - 1) / TB;            // 391
    const int gE4 = (N_EDGES / 4 + TB - 1) / TB;        // 3125
    const int gW  = (N_NODES + 63) / 64;                // 1563
    const int gX  = (N_NODES * 16 + TB - 1) / TB;       // 6250
    const int gG  = (N_NODES * 8) / TB;                 // 3125 exact

    // fork/join resources (created per call, not destroyed during capture; no dev mem)
    cudaStream_t sB;
    cudaEvent_t evStart, evJoin;
    cudaStreamCreateWithFlags(&sB, cudaStreamNonBlocking);
    cudaEventCreateWithFlags(&evStart, cudaEventDisableTiming);
    cudaEventCreateWithFlags(&evJoin, cudaEventDisableTiming);

    // stream B from t=0: x/W conversion + GEMM1 (graph-independent, raw output)
    cudaEventRecord(evStart, 0);
    cudaStreamWaitEvent(sB, evStart, 0);
    convw_kernel<<<(F_IN * HID + TB - 1) / TB, TB, 0, sB>>>(W1, W2);
    xhalf_kernel<<<gX, TB, 0, sB>>>(x);
    gemm_wmma_kernel<F_IN, true><<<gW, 128, 0, sB>>>();
    cudaEventRecord(evJoin, sB);

    // main: CSR build
    zinit_kernel<<<gN, TB>>>();
    hist_kernel<<<gE4, TB>>>(ei);
    dis_kernel<<<gN, TB>>>();
    scan_local_kernel<<<gN, TB>>>();
    scan_sums_kernel<<<1, 512>>>();
    scan_add_kernel<<<gN, TB>>>();
    fill_kernel<<<gE4, TB>>>(ei);

    cudaStreamWaitEvent(0, evJoin, 0);

    // layer 1 aggregate (fp16 HFMA2 accumulate + fused relu(+b1), fp16 out)
    gather_kernel<1><<<gG, TB>>>(b1, bat);

    // layer 2
    gemm_wmma_kernel<HID, false><<<gW, 128>>>();
    gather_kernel<2><<<gG, TB>>>(b1, bat);   // fused pooling

    // head
    head_kernel<<<N_GRAPHS, 64>>>(bat, b2, Wf1, bf1, Wf2, bf2, out);
}

// round 17
// speedup vs baseline: 1.2813x; 1.0359x over previous
#include <cuda_runtime.h>
#include <cuda_fp16.h>
#include <mma.h>

using namespace nvcuda;

#define N_NODES   100000
#define N_EDGES   3200000
#define F_IN      128
#define HID       64
#define N_GRAPHS  256
#define N_CLASSES 8
#define NB        391            // ceil(N_NODES / 256)

// ---------------- scratch (static device globals; no runtime allocs) ----------------
__device__ int    g_indeg[N_NODES];
__device__ int    g_off[N_NODES];
__device__ int    g_cursor[N_NODES];
__device__ int    g_blocksum[NB];
__device__ float  g_dis[N_NODES];
__device__ __half g_dish[N_NODES];                // fp16 dis (scaleAh broadcast)
__device__ int    g_csr[N_EDGES];
__device__ uint4  g_xh[(size_t)N_NODES * 16];     // fp16 x (128 halves/node)
__device__ __half g_w1h[F_IN * HID];
__device__ __half g_w2h[HID * HID];
__device__ uint4  g_bufAh[(size_t)N_NODES * 8];   // fp16 gemm1 out; scaled by dis via scaleAh
__device__ uint4  g_bufA2h[(size_t)N_NODES * 8];  // fp16 gemm2 out, scaled by dis (gather2 src)
__device__ uint4  g_bufH[(size_t)N_NODES * 8];    // fp16 relu(gather1 + b1)  (gemm2 input)
__device__ float  g_pooled[N_GRAPHS * HID];       // fused pooling accumulator

// ---------------- stream-B prepass: W -> fp16 ----------------
__global__ void convw_kernel(const float* __restrict__ W1, const float* __restrict__ W2) {
    int i = blockIdx.x * blockDim.x + threadIdx.x;
    if (i < F_IN * HID) g_w1h[i] = __float2half(W1[i]);
    if (i < HID * HID) g_w2h[i] = __float2half(W2[i]);
}

// ---------------- stream-B prepass: x -> fp16 (8 floats/thread) ----------------
__global__ void xhalf_kernel(const float* __restrict__ x) {
    int i = blockIdx.x * blockDim.x + threadIdx.x;   // over N_NODES*16
    if (i >= N_NODES * 16) return;
    float4 a = ((const float4*)x)[(size_t)i * 2];
    float4 b = ((const float4*)x)[(size_t)i * 2 + 1];
    union { uint4 u; __half2 h[4]; } pk;
    pk.h[0] = __float22half2_rn(make_float2(a.x, a.y));
    pk.h[1] = __float22half2_rn(make_float2(a.z, a.w));
    pk.h[2] = __float22half2_rn(make_float2(b.x, b.y));
    pk.h[3] = __float22half2_rn(make_float2(b.z, b.w));
    g_xh[i] = pk.u;
}

// ---------------- stream-B: bufAh[n] *= dish[n] (after gemm1 + dis) ----------------
__global__ void scaleAh_kernel() {
    int i = blockIdx.x * blockDim.x + threadIdx.x;   // over N_NODES*8
    if (i >= N_NODES * 8) return;
    int n = i >> 3;
    __half2 s = __half2half2(g_dish[n]);
    union { uint4 u; __half2 h[4]; } pk;
    pk.u = g_bufAh[i];
#pragma unroll
    for (int p = 0; p < 4; ++p) pk.h[p] = __hmul2(pk.h[p], s);
    g_bufAh[i] = pk.u;
}

// ---------------- init: zero indeg + pooled ----------------
__global__ void zinit_kernel() {
    int i = blockIdx.x * blockDim.x + threadIdx.x;
    if (i < N_NODES) g_indeg[i] = 0;
    if (i < N_GRAPHS * HID) g_pooled[i] = 0.0f;
}

// ---------------- in-degree histogram over dst (4 edges/thread, int4 loads) ----------------
__global__ void hist_kernel(const int* __restrict__ ei) {
    int e = blockIdx.x * blockDim.x + threadIdx.x;
    if (e >= N_EDGES / 4) return;
    int4 dd = ((const int4*)(ei + N_EDGES))[e];
    atomicAdd(&g_indeg[dd.x], 1);
    atomicAdd(&g_indeg[dd.y], 1);
    atomicAdd(&g_indeg[dd.z], 1);
    atomicAdd(&g_indeg[dd.w], 1);
}

// ---------------- dis = rsqrt(indeg + 1), fp32 + fp16 ----------------
__global__ void dis_kernel() {
    int i = blockIdx.x * blockDim.x + threadIdx.x;
    if (i < N_NODES) {
        float d = rsqrtf((float)(g_indeg[i] + 1));
        g_dis[i] = d;
        g_dish[i] = __float2half(d);
    }
}

// ---------------- scan pass 1: per-block exclusive scan + block sums ----------------
__global__ void scan_local_kernel() {
    __shared__ int s[256];
    int i = blockIdx.x * 256 + threadIdx.x;
    int v = (i < N_NODES) ? g_indeg[i] : 0;
    s[threadIdx.x] = v;
    __syncthreads();
    for (int d = 1; d < 256; d <<= 1) {
        int t = (threadIdx.x >= d) ? s[threadIdx.x - d] : 0;
        __syncthreads();
        s[threadIdx.x] += t;
        __syncthreads();
    }
    if (i < N_NODES) g_off[i] = s[threadIdx.x] - v;
    if (threadIdx.x == 255) g_blocksum[blockIdx.x] = s[255];
}

__global__ void scan_sums_kernel() {
    __shared__ int s[512];
    int i = threadIdx.x;
    int v = (i < NB) ? g_blocksum[i] : 0;
    s[i] = v;
    __syncthreads();
    for (int d = 1; d < 512; d <<= 1) {
        int t = (i >= d) ? s[i - d] : 0;
        __syncthreads();
        s[i] += t;
        __syncthreads();
    }
    if (i < NB) g_blocksum[i] = s[i] - v;
}

__global__ void scan_add_kernel() {
    int i = blockIdx.x * 256 + threadIdx.x;
    if (i >= N_NODES) return;
    int o = g_off[i] + g_blocksum[blockIdx.x];
    g_off[i] = o;
    g_cursor[i] = o;
}

// ---------------- CSR fill (4 edges/thread, int4 loads) ----------------
__global__ void fill_kernel(const int* __restrict__ ei) {
    int e = blockIdx.x * blockDim.x + threadIdx.x;
    if (e >= N_EDGES / 4) return;
    int4 ss = ((const int4*)ei)[e];
    int4 dd = ((const int4*)(ei + N_EDGES))[e];
    g_csr[atomicAdd(&g_cursor[dd.x], 1)] = ss.x;
    g_csr[atomicAdd(&g_cursor[dd.y], 1)] = ss.y;
    g_csr[atomicAdd(&g_cursor[dd.z], 1)] = ss.z;
    g_csr[atomicAdd(&g_cursor[dd.w], 1)] = ss.w;
}

// ---------------- wmma GEMM (all-fp16 inputs, vector loads) ----------------
// LAYER1: A = g_xh, W = g_w1h, out = g_bufAh raw (scaled later by scaleAh)
// else  : A = g_bufH, W = g_w2h, out = g_bufA2h scaled by dis in epilogue
template<int K, bool LAYER1>
__global__ void __launch_bounds__(128) gemm_wmma_kernel() {
    constexpr int ALD = K + 8;           // halves
    constexpr int WLD = 72;              // halves
    constexpr int RU  = K / 8;           // uint4 per A row
    constexpr int A_BYTES   = 64 * ALD * 2;
    constexpr int OUT_BYTES = 64 * 64 * 4;
    constexpr int R1 = (A_BYTES > OUT_BYTES) ? A_BYTES : OUT_BYTES;
    __shared__ char s_mem[R1 + K * WLD * 2];

    __half* sA   = (__half*)s_mem;
    float*  sOut = (float*)s_mem;                 // aliases sA (sync-separated)
    __half* sW   = (__half*)(s_mem + R1);

    int tid = threadIdx.x;
    int block0 = blockIdx.x * 64;

    const uint4* wsrc = (const uint4*)(LAYER1 ? g_w1h : g_w2h);
    for (int j = tid; j < K * 64 / 8; j += 128) {
        int r = j >> 3, c8 = j & 7;
        *(uint4*)(sW + r * WLD + c8 * 8) = wsrc[j];
    }

    const uint4* asrc = LAYER1 ? g_xh : g_bufH;
    for (int j = tid; j < 64 * RU; j += 128) {
        int r = j / RU, u = j % RU;
        int gr = block0 + r; if (gr >= N_NODES) gr = N_NODES - 1;
        *(uint4*)(sA + r * ALD + u * 8) = asrc[(size_t)gr * RU + u];
    }
    __syncthreads();

    int warp = tid >> 5;
    int wrow = warp * 16;

    wmma::fragment<wmma::accumulator, 16, 16, 16, float> acc[4];
#pragma unroll
    for (int n = 0; n < 4; ++n) wmma::fill_fragment(acc[n], 0.0f);

    wmma::fragment<wmma::matrix_a, 16, 16, 16, __half, wmma::row_major> fa;
    wmma::fragment<wmma::matrix_b, 16, 16, 16, __half, wmma::row_major> fb;
#pragma unroll
    for (int kf = 0; kf < K / 16; ++kf) {
        wmma::load_matrix_sync(fa, sA + wrow * ALD + kf * 16, ALD);
#pragma unroll
        for (int n = 0; n < 4; ++n) {
            wmma::load_matrix_sync(fb, sW + kf * 16 * WLD + n * 16, WLD);
            wmma::mma_sync(acc[n], fa, fb, acc[n]);
        }
    }

    __syncthreads();
#pragma unroll
    for (int n = 0; n < 4; ++n)
        wmma::store_matrix_sync(sOut + wrow * 64 + n * 16, acc[n], 64, wmma::mem_row_major);
    __syncthreads();

    int r  = tid >> 1;
    int hf = tid & 1;
    int gr = block0 + r;
    if (gr < N_NODES) {
        float s = LAYER1 ? 1.0f : g_dis[gr];
        const float* row = sOut + r * 64 + hf * 32;
        union { uint4 u; __half2 h[4]; } pk;
#pragma unroll
        for (int q = 0; q < 4; ++q) {
#pragma unroll
            for (int p = 0; p < 4; ++p)
                pk.h[p] = __float22half2_rn(make_float2(row[q*8 + p*2] * s, row[q*8 + p*2 + 1] * s));
            uint4* dst = LAYER1 ? g_bufAh : g_bufA2h;
            dst[(size_t)gr * 8 + hf * 4 + q] = pk.u;
        }
    }
}

// ---------------- gather (both sources pre-scaled; pure HADD2 accumulate) ----------------
__device__ __forceinline__ void acc_row(float* acc, uint4 v) {
    union { uint4 u; __half2 h[4]; } pk; pk.u = v;
#pragma unroll
    for (int p = 0; p < 4; ++p) {
        float2 f = __half22float2(pk.h[p]);
        acc[p * 2]     += f.x;
        acc[p * 2 + 1] += f.y;
    }
}

// MODE 1: src g_bufAh (dis-scaled); out = fp16(relu(acc*dn + b1)) -> g_bufH
// MODE 2: src g_bufA2h (dis-scaled); pooled[batch[n]] += acc*dn (fused pooling)
template<int MODE>
__global__ void __launch_bounds__(256) gather_kernel(const float* __restrict__ b1,
                                                     const int* __restrict__ batch) {
    int t = blockIdx.x * 256 + threadIdx.x;
    int n = t >> 3;                 // 8 threads/node; grid covers exactly N_NODES*8
    int lane = t & 7;

    const uint4* src = (MODE == 1) ? g_bufAh : g_bufA2h;

    int st  = g_off[n];
    int deg = g_indeg[n];
    float dn = g_dis[n];

    float acc[8];
#pragma unroll
    for (int p = 0; p < 8; ++p) acc[p] = 0.0f;
    acc_row(acc, src[(size_t)n * 8 + lane]);      // self loop (pre-scaled) in fp32

    __half2 h[4];
#pragma unroll
    for (int p = 0; p < 4; ++p) h[p] = __float2half2_rn(0.0f);

    int j = 0;
    for (; j + 8 <= deg; j += 8) {
        int sidx[8];
#pragma unroll
        for (int i = 0; i < 8; ++i) sidx[i] = g_csr[st + j + i];
        uint4 v[8];
#pragma unroll
        for (int i = 0; i < 8; ++i) v[i] = src[(size_t)sidx[i] * 8 + lane];
#pragma unroll
        for (int i = 0; i < 8; ++i) {
            union { uint4 u; __half2 hh[4]; } pk; pk.u = v[i];
#pragma unroll
            for (int p = 0; p < 4; ++p) h[p] = __hadd2(h[p], pk.hh[p]);
        }
        // fold into fp32 master, reset fp16 accumulator
#pragma unroll
        for (int p = 0; p < 4; ++p) {
            float2 f = __half22float2(h[p]);
            acc[p * 2]     += f.x;
            acc[p * 2 + 1] += f.y;
            h[p] = __float2half2_rn(0.0f);
        }
    }
    for (; j < deg; ++j) {
        int s = g_csr[st + j];
        union { uint4 u; __half2 hh[4]; } pk; pk.u = src[(size_t)s * 8 + lane];
#pragma unroll
        for (int p = 0; p < 4; ++p) h[p] = __hadd2(h[p], pk.hh[p]);
    }
#pragma unroll
    for (int p = 0; p < 4; ++p) {
        float2 f = __half22float2(h[p]);
        acc[p * 2]     += f.x;
        acc[p * 2 + 1] += f.y;
    }

    if (MODE == 1) {
        union { uint4 u; __half2 h[4]; } pk;
#pragma unroll
        for (int p = 0; p < 4; ++p) {
            float v0 = fmaxf(acc[p*2]     * dn + b1[lane*8 + p*2],     0.0f);
            float v1 = fmaxf(acc[p*2 + 1] * dn + b1[lane*8 + p*2 + 1], 0.0f);
            pk.h[p] = __float22half2_rn(make_float2(v0, v1));
        }
        g_bufH[(size_t)n * 8 + lane] = pk.u;
    } else {
#pragma unroll
        for (int p = 0; p < 8; ++p) acc[p] *= dn;
        int g = batch[n];
        unsigned eq = __match_any_sync(0xFFFFFFFFu, g);
        if (eq == 0xFFFFFFFFu) {
#pragma unroll
            for (int p = 0; p < 8; ++p) {
                acc[p] += __shfl_xor_sync(0xFFFFFFFFu, acc[p], 8);
                acc[p] += __shfl_xor_sync(0xFFFFFFFFu, acc[p], 16);
            }
            if ((threadIdx.x & 31) < 8) {
#pragma unroll
                for (int p = 0; p < 8; ++p)
                    atomicAdd(&g_pooled[g * HID + lane * 8 + p], acc[p]);
            }
        } else {
#pragma unroll
            for (int p = 0; p < 8; ++p)
                atomicAdd(&g_pooled[g * HID + lane * 8 + p], acc[p]);
        }
    }
}

// ---------------- head: mean + b2, fc1(relu), fc2 -> out ----------------
__global__ void __launch_bounds__(64) head_kernel(const int* __restrict__ batch,
                                                  const float* __restrict__ b2,
                                                  const float* __restrict__ Wf1,
                                                  const float* __restrict__ bf1,
                                                  const float* __restrict__ Wf2,
                                                  const float* __restrict__ bf2,
                                                  float* __restrict__ out) {
    __shared__ int   s_bound[2];
    __shared__ float s_mean[HID];
    __shared__ float s_h1[32];

    int g = blockIdx.x;
    int c = threadIdx.x;

    if (c < 2) {
        int target = g + c;
        int lo = 0, hi = N_NODES;
        while (lo < hi) {
            int mid = (lo + hi) >> 1;
            if (batch[mid] < target) lo = mid + 1; else hi = mid;
        }
        s_bound[c] = lo;
    }
    __syncthreads();

    int cnt = s_bound[1] - s_bound[0];
    float invc = (cnt > 0) ? (1.0f / (float)cnt) : 0.0f;
    s_mean[c] = (cnt > 0) ? (g_pooled[g * HID + c] * invc + b2[c]) : 0.0f;
    __syncthreads();

    if (c < 32) {
        float h1 = bf1[c];
#pragma unroll
        for (int k = 0; k < HID; ++k) h1 += s_mean[k] * Wf1[k * 32 + c];
        s_h1[c] = fmaxf(h1, 0.0f);
    }
    __syncthreads();

    if (c < N_CLASSES) {
        float o = bf2[c];
#pragma unroll
        for (int k = 0; k < 32; ++k) o += s_h1[k] * Wf2[k * N_CLASSES + c];
        out[g * N_CLASSES + c] = o;
    }
}

// ---------------- launch ----------------
extern "C" void kernel_launch(void* const* d_in, const int* in_sizes, int n_in,
                              void* d_out, int out_size) {
    const float* x   = (const float*)d_in[0];
    const int*   ei  = (const int*)d_in[1];     // int32 (JAX x64 disabled)
    const int*   bat = (const int*)d_in[2];     // int32
    const float* W1  = (const float*)d_in[3];
    const float* b1  = (const float*)d_in[4];
    const float* W2  = (const float*)d_in[5];
    const float* b2  = (const float*)d_in[6];
    const float* Wf1 = (const float*)d_in[7];
    const float* bf1 = (const float*)d_in[8];
    const float* Wf2 = (const float*)d_in[9];
    const float* bf2 = (const float*)d_in[10];
    float* out = (float*)d_out;

    const int TB  = 256;
    const int gN  = (N_NODES + TB - 1) / TB;            // 391
    const int gE4 = (N_EDGES / 4 + TB - 1) / TB;        // 3125
    const int gW  = (N_NODES + 63) / 64;                // 1563
    const int gX  = (N_NODES * 16 + TB - 1) / TB;       // 6250
    const int gS  = (N_NODES * 8 + TB - 1) / TB;        // 3125 (scaleAh)
    const int gG  = (N_NODES * 8) / TB;                 // 3125 exact

    // fork/join resources (created per call, not destroyed during capture; no dev mem)
    cudaStream_t sB;
    cudaEvent_t evStart, evDis, evJoin;
    cudaStreamCreateWithFlags(&sB, cudaStreamNonBlocking);
    cudaEventCreateWithFlags(&evStart, cudaEventDisableTiming);
    cudaEventCreateWithFlags(&evDis,   cudaEventDisableTiming);
    cudaEventCreateWithFlags(&evJoin,  cudaEventDisableTiming);

    // stream B from t=0: x/W conversion + GEMM1 (graph-independent, raw output)
    cudaEventRecord(evStart, 0);
    cudaStreamWaitEvent(sB, evStart, 0);
    convw_kernel<<<(F_IN * HID + TB - 1) / TB, TB, 0, sB>>>(W1, W2);
    xhalf_kernel<<<gX, TB, 0, sB>>>(x);
    gemm_wmma_kernel<F_IN, true><<<gW, 128, 0, sB>>>();

    // main: CSR build
    zinit_kernel<<<gN, TB>>>();
    hist_kernel<<<gE4, TB>>>(ei);
    dis_kernel<<<gN, TB>>>();
    cudaEventRecord(evDis, 0);
    scan_local_kernel<<<gN, TB>>>();
    scan_sums_kernel<<<1, 512>>>();
    scan_add_kernel<<<gN, TB>>>();
    fill_kernel<<<gE4, TB>>>(ei);

    // stream B: scale gemm1 output by dis (needs dis + gemm1; in prefix slack)
    cudaStreamWaitEvent(sB, evDis, 0);
    scaleAh_kernel<<<gS, TB, 0, sB>>>();
    cudaEventRecord(evJoin, sB);

    cudaStreamWaitEvent(0, evJoin, 0);

    // layer 1 aggregate (pure HADD2 + fused relu(+b1), fp16 out)
    gather_kernel<1><<<gG, TB>>>(b1, bat);

    // layer 2
    gemm_wmma_kernel<HID, false><<<gW, 128>>>();
    gather_kernel<2><<<gG, TB>>>(b1, bat);   // fused pooling

    // head
    head_kernel<<<N_GRAPHS, 64>>>(bat, b2, Wf1, bf1, Wf2, bf2, out);
}